// round 16
// baseline (speedup 1.0000x reference)
#include <cuda_runtime.h>
#include <cstdint>

#define NN    8192
#define FIN   128
#define FOUT  64
#define ALPHA 0.2f
#define LOG2E 1.4426950408889634f

#define TI    128
#define SPLIT 4
#define JH    (NN/SPLIT)   // 2048
#define KC    32
#define NCH   (JH/KC)      // 64
#define NSTAGE 4
#define NSTAGE_LOG2 2

#define NTHREADS 320       // 8 consumer warps + 2 producer warps

#define B_STRIDE 40        // halves per B row (32 + pad) -> 80B
#define B_BUF  (FOUT*B_STRIDE*2)        // 5120
#define EF_BUF 256                      // 128 used
#define MK_BUF 512                      // 128 row bitmasks (u32)
#define OFF_EF B_BUF
#define OFF_MK (B_BUF + EF_BUF)
#define STAGE_BYTES (B_BUF + EF_BUF + MK_BUF)  // 5888
#define MBAR_OFF   (NSTAGE*STAGE_BYTES)        // 23552
#define GAT_SMEM   (MBAR_OFF + NSTAGE*16 + 256)

// ---------------- device scratch ----------------
__device__ __align__(256) uint16_t g_hT16[(size_t)FOUT * NN];  // h^T fp16 [f][node]
__device__ __align__(256) uint2 g_EF1p[NN];     // {E1 dup f16x2, F1 dup f16x2}
__device__ __align__(256) uint2 g_E2Fp[NN/2];   // {E2 pair f16x2, F2 pair f16x2}
__device__ float  g_part[SPLIT][(size_t)NN * FOUT];
__device__ float  g_wsum[SPLIT][NN];
__device__ int    g_cnt[NN / TI];

// ---------------- helpers ----------------
__device__ __forceinline__ float ex2f(float x) {
    float r; asm("ex2.approx.ftz.f32 %0, %1;" : "=f"(r) : "f"(x)); return r;
}
__device__ __forceinline__ uint32_t smem_u32(const void* p) {
    uint32_t a;
    asm("{ .reg .u64 t; cvta.to.shared.u64 t, %1; cvt.u32.u64 %0, t; }" : "=r"(a) : "l"(p));
    return a;
}
__device__ __forceinline__ uint16_t f2h(float x) {
    uint16_t r; asm("cvt.rn.f16.f32 %0, %1;" : "=h"(r) : "f"(x)); return r;
}
__device__ __forceinline__ uint32_t pkh2(float lo, float hi) {
    uint32_t r; asm("cvt.rn.f16x2.f32 %0, %1, %2;" : "=r"(r) : "f"(hi), "f"(lo)); return r;
}
__device__ __forceinline__ uint32_t hmul2(uint32_t a, uint32_t b) {
    uint32_t r; asm("mul.f16x2 %0, %1, %2;" : "=r"(r) : "r"(a), "r"(b)); return r;
}
__device__ __forceinline__ uint32_t hmax2(uint32_t a, uint32_t b) {
    uint32_t r; asm("max.f16x2 %0, %1, %2;" : "=r"(r) : "r"(a), "r"(b)); return r;
}
// masked w pair from a row bitmask: bits (j) and (j+1)
__device__ __forceinline__ uint32_t wpairm(uint32_t e1E, uint32_t e1F,
                                           uint32_t e2, uint32_t f2,
                                           uint32_t mask, int j) {
    const uint32_t b0 = (mask >> j) & 1u;
    const uint32_t b1 = (mask >> (j + 1)) & 1u;
    const uint32_t m = b0 * 0x3C00u + b1 * 0x3C000000u;
    return hmul2(hmax2(hmul2(e1E, e2), hmul2(e1F, f2)), m);
}
// coalesced streaming int4 global load
__device__ __forceinline__ int4 ldcs4(const int* p) {
    int4 v;
    asm volatile("ld.global.cs.v4.u32 {%0,%1,%2,%3}, [%4];"
                 : "=r"(v.x), "=r"(v.y), "=r"(v.z), "=r"(v.w) : "l"(p));
    return v;
}
__device__ __forceinline__ void sts32(uint32_t a, uint32_t v) {
    asm volatile("st.shared.u32 [%0], %1;" :: "r"(a), "r"(v) : "memory");
}

#define CP16(dst, src) \
    asm volatile("cp.async.cg.shared.global [%0], [%1], 16;" :: "r"(dst), "l"(src) : "memory")

// mbarrier ops
#define MBAR_INIT(mb, cnt) \
    asm volatile("mbarrier.init.shared.b64 [%0], %1;" :: "r"((uint32_t)(mb)), "r"((uint32_t)(cnt)) : "memory")
#define MBAR_ARRIVE(mb) \
    asm volatile("mbarrier.arrive.shared.b64 _, [%0];" :: "r"((uint32_t)(mb)) : "memory")
#define CPASYNC_MBAR_ARRIVE(mb) \
    asm volatile("cp.async.mbarrier.arrive.noinc.shared.b64 [%0];" :: "r"((uint32_t)(mb)) : "memory")
#define MBAR_WAIT(mb, parity) do { \
    uint32_t _m = (uint32_t)(mb); uint32_t _p = (uint32_t)(parity); uint32_t _d; \
    asm volatile("{\n\t.reg .pred p;\n\tmbarrier.try_wait.parity.acquire.cta.shared::cta.b64 p, [%1], %2;\n\tselp.b32 %0, 1, 0, p;\n\t}" \
        : "=r"(_d) : "r"(_m), "r"(_p) : "memory"); \
    if (!_d) { \
        asm volatile("{\n\t.reg .pred P1;\n\tWL_%=:\n\tmbarrier.try_wait.parity.acquire.cta.shared::cta.b64 P1, [%0], %1;\n\t@P1 bra.uni WD_%=;\n\tbra.uni WL_%=;\n\tWD_%=:\n\t}" \
            :: "r"(_m), "r"(_p) : "memory"); \
    } } while (0)

__device__ __forceinline__ uint32_t lds_u32(uint32_t a) {
    uint32_t v; asm volatile("ld.shared.b32 %0, [%1];" : "=r"(v) : "r"(a)); return v;
}
__device__ __forceinline__ uint2 lds_u64(uint32_t a) {
    uint2 v; asm volatile("ld.shared.v2.u32 {%0,%1}, [%2];" : "=r"(v.x), "=r"(v.y) : "r"(a)); return v;
}

#define MMA_F16(c, a0, a1, a2, a3, b0, b1) \
    asm volatile("mma.sync.aligned.m16n8k16.row.col.f32.f16.f16.f32 " \
        "{%0,%1,%2,%3}, {%4,%5,%6,%7}, {%8,%9}, {%0,%1,%2,%3};" \
        : "+f"((c)[0]), "+f"((c)[1]), "+f"((c)[2]), "+f"((c)[3]) \
        : "r"(a0), "r"(a1), "r"(a2), "r"(a3), "r"(b0), "r"(b1))

// ===================== K1: projection + node tables + counter reset =====================
__global__ __launch_bounds__(256) void k_proj(const float* __restrict__ X,
                                              const float* __restrict__ W,
                                              const float* __restrict__ a1,
                                              const float* __restrict__ a2) {
    __shared__ float Ws[FIN * FOUT];
    __shared__ float Xs[FIN * 17];
    __shared__ uint16_t hTs[FOUT * 20];

    const int tid = threadIdx.x;
    const int i0 = blockIdx.x * 16;

    if (blockIdx.x == 0 && tid < NN / TI) g_cnt[tid] = 0;

    {
        const float4* W4 = (const float4*)W;
        float4* Ws4 = (float4*)Ws;
#pragma unroll
        for (int k = 0; k < 8; k++) Ws4[tid + k * 256] = W4[tid + k * 256];
    }
    {
        const int row = tid & 15;
        const int q0 = tid >> 4;
#pragma unroll
        for (int m = 0; m < 2; m++) {
            const int q = q0 + 16 * m;
            const float4 v = *(const float4*)(X + (size_t)(i0 + row) * FIN + 4 * q);
            Xs[(4 * q + 0) * 17 + row] = v.x;
            Xs[(4 * q + 1) * 17 + row] = v.y;
            Xs[(4 * q + 2) * 17 + row] = v.z;
            Xs[(4 * q + 3) * 17 + row] = v.w;
        }
    }
    __syncthreads();

    const int rg = tid >> 4;
    const int cg = tid & 15;
    const float4* Ws4 = (const float4*)Ws;

    float aA[4] = {0.f, 0.f, 0.f, 0.f}, aB[4] = {0.f, 0.f, 0.f, 0.f};
#pragma unroll 8
    for (int k = 0; k < FIN; k += 2) {
        const float x0 = Xs[k * 17 + rg];
        const float x1 = Xs[(k + 1) * 17 + rg];
        const float4 w0 = Ws4[k * 16 + cg];
        const float4 w1 = Ws4[(k + 1) * 16 + cg];
        aA[0] += x0 * w0.x; aA[1] += x0 * w0.y; aA[2] += x0 * w0.z; aA[3] += x0 * w0.w;
        aB[0] += x1 * w1.x; aB[1] += x1 * w1.y; aB[2] += x1 * w1.z; aB[3] += x1 * w1.w;
    }
    float acc[4];
#pragma unroll
    for (int c = 0; c < 4; c++) acc[c] = aA[c] + aB[c];

#pragma unroll
    for (int c = 0; c < 4; c++) hTs[(4 * cg + c) * 20 + rg] = f2h(acc[c]);

    const float4 a1v = ((const float4*)a1)[cg];
    const float4 a2v = ((const float4*)a2)[cg];
    float v1 = acc[0] * a1v.x + acc[1] * a1v.y + acc[2] * a1v.z + acc[3] * a1v.w;
    float v2 = acc[0] * a2v.x + acc[1] * a2v.y + acc[2] * a2v.z + acc[3] * a2v.w;
#pragma unroll
    for (int s = 8; s > 0; s >>= 1) {
        v1 += __shfl_xor_sync(0xffffffffu, v1, s, 16);
        v2 += __shfl_xor_sync(0xffffffffu, v2, s, 16);
    }

    const float s1L = v1 * LOG2E;
    const float s2L = v2 * LOG2E;
    const float E1 = ex2f(s1L), F1 = ex2f(ALPHA * s1L);
    const float E2 = ex2f(s2L), F2 = ex2f(ALPHA * s2L);
    const float E2o = __shfl_xor_sync(0xffffffffu, E2, 16);
    const float F2o = __shfl_xor_sync(0xffffffffu, F2, 16);
    if (cg == 0) {
        g_EF1p[i0 + rg] = make_uint2(pkh2(E1, E1), pkh2(F1, F1));
        if ((tid & 31) == 0)
            g_E2Fp[(i0 + rg) >> 1] = make_uint2(pkh2(E2, E2o), pkh2(F2, F2o));
    }
    __syncthreads();

    {
        const int f = tid >> 2;
        const int sg = tid & 3;
        const uint2 v = *(const uint2*)&hTs[f * 20 + 4 * sg];
        *(uint2*)(g_hT16 + (size_t)f * NN + i0 + 4 * sg) = v;
    }
}

// ===================== K2: warp-specialized GAT; A packed to bitmasks by producers =====================
__global__ __launch_bounds__(NTHREADS, 2) void k_gat(const int* __restrict__ A,
                                                     float* __restrict__ out) {
    extern __shared__ char sm[];
    const uint32_t sb0 = smem_u32(sm);
    const uint32_t sb = (sb0 + 127u) & ~127u;
    const uint32_t mb = sb + MBAR_OFF;        // full[s]=mb+s*16, empty[s]=mb+s*16+8

    const int tid  = threadIdx.x;
    const int wid  = tid >> 5;
    const int lane = tid & 31;
    const int ib   = blockIdx.x >> 2;
    const int sk   = blockIdx.x & 3;
    const int i0   = ib * TI;
    const int j0   = sk * JH;

    if (tid == 0) {
#pragma unroll
        for (int s = 0; s < NSTAGE; s++) {
            MBAR_INIT(mb + s * 16,     66);   // full: 64 cp.async noinc + 2 mask arrives
            MBAR_INIT(mb + s * 16 + 8, 8);    // empty: 8 consumer warps
        }
    }
    __syncthreads();

    if (wid >= 8) {
        // ================= PRODUCER (2 warps, 64 threads) =================
        const int p  = tid - 256;                 // 0..63
        const int lp = p & 31;
        const int pw = p >> 5;                    // producer warp id
        const int rbase = pw * 64;                // this warp packs rows rbase..rbase+63
        const uint16_t* hSrc = g_hT16 + j0;
        // coalesced A base: LDG.128 i covers rows rbase+4i..+3; lane octets = row segments
        const int* aPtr = A + (size_t)(i0 + rbase + (lp >> 3)) * NN + j0 + 4 * (lp & 7);

        int4 av[16];
#define LOADA(T) do {                                                      \
            const int _o = (T) * KC;                                       \
            _Pragma("unroll")                                              \
            for (int i = 0; i < 16; i++)                                   \
                av[i] = ldcs4(aPtr + (size_t)(4 * i) * NN + _o);           \
        } while (0)

        LOADA(0);

        for (int t = 0; t < NCH; t++) {
            const int s = t & (NSTAGE - 1);
            const int k = t >> NSTAGE_LOG2;
            if (k > 0) MBAR_WAIT(mb + s * 16 + 8, (k - 1) & 1);

            const uint32_t base = sb + (uint32_t)(s * STAGE_BYTES);
            const int jo = t * KC;
            // B: 64 f-rows x 64B; thread p -> f row p, 4 segments
#pragma unroll
            for (int g = 0; g < 4; g++) {
                CP16(base + (uint32_t)(p * B_STRIDE + g * 8) * 2,
                     hSrc + (size_t)p * NN + jo + g * 8);
            }
            if (p < 8)
                CP16(base + OFF_EF + (uint32_t)p * 16,
                     g_E2Fp + ((j0 + jo) >> 1) + p * 2);
            CPASYNC_MBAR_ARRIVE(mb + s * 16);

            // A pack (chunk t, from registers loaded last iteration)
#pragma unroll
            for (int i = 0; i < 16; i++) {
                const int4 v = av[i];
                uint32_t m = (v.x > 0 ? 1u : 0u) | (v.y > 0 ? 2u : 0u) |
                             (v.z > 0 ? 4u : 0u) | (v.w > 0 ? 8u : 0u);
                m <<= 4 * (lp & 7);
                m |= __shfl_xor_sync(0xffffffffu, m, 1);
                m |= __shfl_xor_sync(0xffffffffu, m, 2);
                m |= __shfl_xor_sync(0xffffffffu, m, 4);
                if ((lp & 7) == 0)
                    sts32(base + OFF_MK + (uint32_t)(rbase + 4 * i + (lp >> 3)) * 4, m);
            }
            __syncwarp();
            if (lp == 0) MBAR_ARRIVE(mb + s * 16);   // release: publishes mask STS

            if (t + 1 < NCH) LOADA(t + 1);            // prefetch next chunk's A
        }
    } else {
        // ================= CONSUMER (8 warps, m32 x n32 each) =================
        const int qr = lane >> 2;
        const int qc = lane & 3;
        const int mg = wid >> 1;
        const int ng = wid & 1;

        uint32_t e1E[4], e1F[4];
#pragma unroll
        for (int k = 0; k < 4; k++) {
            const uint2 v = g_EF1p[i0 + mg * 32 + qr + 8 * k];
            e1E[k] = v.x; e1F[k] = v.y;
        }

        float acc[2][4][4];
        float accO[2][4];
#pragma unroll
        for (int mt = 0; mt < 2; mt++) {
#pragma unroll
            for (int nt = 0; nt < 4; nt++)
#pragma unroll
                for (int k = 0; k < 4; k++) acc[mt][nt][k] = 0.f;
#pragma unroll
            for (int k = 0; k < 4; k++) accO[mt][k] = 0.f;
        }
        const uint32_t kOnes = 0x3C003C00u;

        for (int t = 0; t < NCH; t++) {
            const int s = t & (NSTAGE - 1);
            const int k = t >> NSTAGE_LOG2;
            MBAR_WAIT(mb + s * 16, k & 1);

            const uint32_t bB = sb + (uint32_t)(s * STAGE_BYTES);
            const uint32_t eB = bB + OFF_EF;
            const uint32_t mkB = bB + OFF_MK;

            // row bitmasks for this lane's 4 rows
            const uint32_t mk0 = lds_u32(mkB + (uint32_t)(mg * 32 + qr) * 4);
            const uint32_t mk1 = lds_u32(mkB + (uint32_t)(mg * 32 + 8 + qr) * 4);
            const uint32_t mk2 = lds_u32(mkB + (uint32_t)(mg * 32 + 16 + qr) * 4);
            const uint32_t mk3 = lds_u32(mkB + (uint32_t)(mg * 32 + 24 + qr) * 4);

#pragma unroll
            for (int ks = 0; ks < 2; ks++) {
                const int j2 = 16 * ks + 2 * qc;
                const uint2 efL = lds_u64(eB + (uint32_t)(j2 >> 1) * 8);
                const uint2 efH = lds_u64(eB + (uint32_t)((j2 + 8) >> 1) * 8);

                uint32_t b0[4], b1[4];
#pragma unroll
                for (int nt = 0; nt < 4; nt++) {
                    const int f = ng * 32 + nt * 8 + qr;
                    const uint32_t hb = bB + (uint32_t)(f * B_STRIDE + j2) * 2;
                    b0[nt] = lds_u32(hb);
                    b1[nt] = lds_u32(hb + 16);
                }

#pragma unroll
                for (int mt = 0; mt < 2; mt++) {
                    const uint32_t mlo = mt ? mk2 : mk0;
                    const uint32_t mhi = mt ? mk3 : mk1;
                    const uint32_t a0 = wpairm(e1E[2*mt],   e1F[2*mt],   efL.x, efL.y, mlo, j2);
                    const uint32_t a1 = wpairm(e1E[2*mt+1], e1F[2*mt+1], efL.x, efL.y, mhi, j2);
                    const uint32_t a2 = wpairm(e1E[2*mt],   e1F[2*mt],   efH.x, efH.y, mlo, j2 + 8);
                    const uint32_t a3 = wpairm(e1E[2*mt+1], e1F[2*mt+1], efH.x, efH.y, mhi, j2 + 8);

#pragma unroll
                    for (int nt = 0; nt < 4; nt++)
                        MMA_F16(acc[mt][nt], a0, a1, a2, a3, b0[nt], b1[nt]);
                    MMA_F16(accO[mt], a0, a1, a2, a3, kOnes, kOnes);
                }
            }
            __syncwarp();
            if (lane == 0) MBAR_ARRIVE(mb + s * 16 + 8);
        }

        // ---- epilogue: store partials ----
        if (ng == 0 && qc == 0) {
            g_wsum[sk][i0 + mg * 32 + qr]      = accO[0][0];
            g_wsum[sk][i0 + mg * 32 + qr + 8]  = accO[0][2];
            g_wsum[sk][i0 + mg * 32 + qr + 16] = accO[1][0];
            g_wsum[sk][i0 + mg * 32 + qr + 24] = accO[1][2];
        }
#pragma unroll
        for (int mt = 0; mt < 2; mt++) {
            float* pr0 = &g_part[sk][(size_t)(i0 + mg * 32 + mt * 16 + qr) * FOUT];
            float* pr1 = &g_part[sk][(size_t)(i0 + mg * 32 + mt * 16 + qr + 8) * FOUT];
#pragma unroll
            for (int nt = 0; nt < 4; nt++) {
                const int c0 = ng * 32 + nt * 8 + 2 * qc;
                *(float2*)(pr0 + c0) = make_float2(acc[mt][nt][0], acc[mt][nt][1]);
                *(float2*)(pr1 + c0) = make_float2(acc[mt][nt][2], acc[mt][nt][3]);
            }
        }
    }

    // ---- last split-K CTA for this i-block combines and divides ----
    __threadfence();
    __syncthreads();
    __shared__ int isLast;
    if (tid == 0) isLast = (atomicAdd(&g_cnt[ib], 1) == SPLIT - 1) ? 1 : 0;
    __syncthreads();
    if (isLast && tid < 256) {
        __threadfence();
#pragma unroll
        for (int k = 0; k < 8; k++) {
            const int idx4 = tid + k * 256;
            const int row = idx4 >> 4;
            const size_t e = (size_t)(i0 + row) * FOUT + (idx4 & 15) * 4;
            float4 s = *(const float4*)&g_part[0][e];
            float den = g_wsum[0][i0 + row];
#pragma unroll
            for (int p = 1; p < SPLIT; p++) {
                const float4 pp = *(const float4*)&g_part[p][e];
                s.x += pp.x; s.y += pp.y; s.z += pp.z; s.w += pp.w;
                den += g_wsum[p][i0 + row];
            }
            const float inv = 1.0f / den;
            *(float4*)(out + e) = make_float4(s.x * inv, s.y * inv, s.z * inv, s.w * inv);
        }
    }
}

extern "C" void kernel_launch(void* const* d_in, const int* in_sizes, int n_in,
                              void* d_out, int out_size) {
    const float* X  = (const float*)d_in[0];
    const int*   A  = (const int*)d_in[1];
    const float* W  = (const float*)d_in[2];
    const float* a1 = (const float*)d_in[3];
    const float* a2 = (const float*)d_in[4];
    float* out = (float*)d_out;

    cudaFuncSetAttribute(k_gat, cudaFuncAttributeMaxDynamicSharedMemorySize, GAT_SMEM);

    k_proj<<<NN / 16, 256>>>(X, W, a1, a2);
    k_gat<<<(NN / TI) * SPLIT, NTHREADS, GAT_SMEM>>>(A, out);
}

// round 17
// speedup vs baseline: 1.4402x; 1.4402x over previous
#include <cuda_runtime.h>
#include <cstdint>

#define NN    8192
#define FIN   128
#define FOUT  64
#define ALPHA 0.2f
#define LOG2E 1.4426950408889634f

#define TI    128
#define SPLIT 4
#define JH    (NN/SPLIT)   // 2048
#define KC    32
#define NCH   (JH/KC)      // 64
#define NSTAGE 4
#define NSTAGE_LOG2 2

#define NTHREADS 320       // 8 consumer warps + 2 producer warps

#define A_STRIDE 40        // ints per A row (32 + pad) -> 160B
#define B_STRIDE 40        // halves per B row (32 + pad) -> 80B
#define A_BUF  (TI*A_STRIDE*4)          // 20480
#define B_BUF  (FOUT*B_STRIDE*2)        // 5120
#define EF_BUF 256                      // 128 used
#define STAGE_BYTES (A_BUF + B_BUF + EF_BUF)   // 25856
#define MBAR_OFF   (NSTAGE*STAGE_BYTES)        // 103424
#define GAT_SMEM   (MBAR_OFF + NSTAGE*16 + 256)

// ---------------- device scratch ----------------
__device__ __align__(256) uint16_t g_hT16[(size_t)FOUT * NN];  // h^T fp16 [f][node]
__device__ __align__(256) uint2 g_EF1p[NN];     // {E1 dup f16x2, F1 dup f16x2}
__device__ __align__(256) uint2 g_E2Fp[NN/2];   // {E2 pair f16x2, F2 pair f16x2}
__device__ float  g_part[SPLIT][(size_t)NN * FOUT];
__device__ float  g_wsum[SPLIT][NN];
__device__ int    g_cnt[NN / TI];

// ---------------- helpers ----------------
__device__ __forceinline__ float ex2f(float x) {
    float r; asm("ex2.approx.ftz.f32 %0, %1;" : "=f"(r) : "f"(x)); return r;
}
__device__ __forceinline__ uint32_t smem_u32(const void* p) {
    uint32_t a;
    asm("{ .reg .u64 t; cvta.to.shared.u64 t, %1; cvt.u32.u64 %0, t; }" : "=r"(a) : "l"(p));
    return a;
}
__device__ __forceinline__ uint16_t f2h(float x) {
    uint16_t r; asm("cvt.rn.f16.f32 %0, %1;" : "=h"(r) : "f"(x)); return r;
}
__device__ __forceinline__ uint32_t pkh2(float lo, float hi) {
    uint32_t r; asm("cvt.rn.f16x2.f32 %0, %1, %2;" : "=r"(r) : "f"(hi), "f"(lo)); return r;
}
__device__ __forceinline__ uint32_t hmul2(uint32_t a, uint32_t b) {
    uint32_t r; asm("mul.f16x2 %0, %1, %2;" : "=r"(r) : "r"(a), "r"(b)); return r;
}
__device__ __forceinline__ uint32_t hmax2(uint32_t a, uint32_t b) {
    uint32_t r; asm("max.f16x2 %0, %1, %2;" : "=r"(r) : "r"(a), "r"(b)); return r;
}
__device__ __forceinline__ uint32_t wpair(uint32_t e1E, uint32_t e1F,
                                          uint32_t e2, uint32_t f2,
                                          int ax, int ay) {
    const uint32_t m = (uint32_t)ax * 0x3C00u + (uint32_t)ay * 0x3C000000u;
    return hmul2(hmax2(hmul2(e1E, e2), hmul2(e1F, f2)), m);
}

#define CP16(dst, src) \
    asm volatile("cp.async.cg.shared.global [%0], [%1], 16;" :: "r"(dst), "l"(src) : "memory")
#define CP_COMMIT() asm volatile("cp.async.commit_group;" ::: "memory")
#define CP_WAIT0()  asm volatile("cp.async.wait_group 0;" ::: "memory")

// mbarrier ops
#define MBAR_INIT(mb, cnt) \
    asm volatile("mbarrier.init.shared.b64 [%0], %1;" :: "r"((uint32_t)(mb)), "r"((uint32_t)(cnt)) : "memory")
#define MBAR_ARRIVE(mb) \
    asm volatile("mbarrier.arrive.shared.b64 _, [%0];" :: "r"((uint32_t)(mb)) : "memory")
#define CPASYNC_MBAR_ARRIVE(mb) \
    asm volatile("cp.async.mbarrier.arrive.noinc.shared.b64 [%0];" :: "r"((uint32_t)(mb)) : "memory")
#define MBAR_WAIT(mb, parity) do { \
    uint32_t _m = (uint32_t)(mb); uint32_t _p = (uint32_t)(parity); uint32_t _d; \
    asm volatile("{\n\t.reg .pred p;\n\tmbarrier.try_wait.parity.shared.b64 p, [%1], %2;\n\tselp.b32 %0, 1, 0, p;\n\t}" \
        : "=r"(_d) : "r"(_m), "r"(_p) : "memory"); \
    if (!_d) { \
        asm volatile("{\n\t.reg .pred P1;\n\tWL_%=:\n\tmbarrier.try_wait.parity.shared.b64 P1, [%0], %1;\n\t@P1 bra.uni WD_%=;\n\tbra.uni WL_%=;\n\tWD_%=:\n\t}" \
            :: "r"(_m), "r"(_p) : "memory"); \
    } } while (0)

__device__ __forceinline__ uint32_t lds_u32(uint32_t a) {
    uint32_t v; asm volatile("ld.shared.b32 %0, [%1];" : "=r"(v) : "r"(a)); return v;
}
__device__ __forceinline__ int2 lds_s64(uint32_t a) {
    int2 v; asm volatile("ld.shared.v2.u32 {%0,%1}, [%2];" : "=r"(v.x), "=r"(v.y) : "r"(a)); return v;
}
__device__ __forceinline__ uint2 lds_u64(uint32_t a) {
    uint2 v; asm volatile("ld.shared.v2.u32 {%0,%1}, [%2];" : "=r"(v.x), "=r"(v.y) : "r"(a)); return v;
}

#define MMA_F16(c, a0, a1, a2, a3, b0, b1) \
    asm volatile("mma.sync.aligned.m16n8k16.row.col.f32.f16.f16.f32 " \
        "{%0,%1,%2,%3}, {%4,%5,%6,%7}, {%8,%9}, {%0,%1,%2,%3};" \
        : "+f"((c)[0]), "+f"((c)[1]), "+f"((c)[2]), "+f"((c)[3]) \
        : "r"(a0), "r"(a1), "r"(a2), "r"(a3), "r"(b0), "r"(b1))

// ===================== K1: projection + node tables + counter reset =====================
// 512 CTAs x 16 rows; cp.async fills (W smem [k][f], X row-major stride 132), broadcast x reads.
__global__ __launch_bounds__(256) void k_proj(const float* __restrict__ X,
                                              const float* __restrict__ W,
                                              const float* __restrict__ a1,
                                              const float* __restrict__ a2) {
    __shared__ float Ws[FIN * FOUT];          // 32 KB  [k][f]
    __shared__ float Xrm[16 * 132];           // 8.25 KB row-major [row][k], stride 132 (==4 mod 32)
    __shared__ uint16_t hTs[FOUT * 20];       // fp16 staging [f][row]

    const int tid = threadIdx.x;
    const int i0 = blockIdx.x * 16;

    if (blockIdx.x == 0 && tid < NN / TI) g_cnt[tid] = 0;

    // --- cp.async fills: W (2048 x 16B) + X (512 x 16B), all in flight together ---
    {
        const uint32_t wdst = smem_u32(Ws);
        const float4* W4 = (const float4*)W;
#pragma unroll
        for (int k = 0; k < 8; k++)
            CP16(wdst + (uint32_t)(tid + k * 256) * 16, W4 + tid + k * 256);

        const uint32_t xdst = smem_u32(Xrm);
        const int row = tid >> 4;
        const int sg = tid & 15;
        const float* xsrc = X + (size_t)(i0 + row) * FIN;
        CP16(xdst + (uint32_t)(row * 132 + sg * 4) * 4, xsrc + sg * 4);
        CP16(xdst + (uint32_t)(row * 132 + (sg + 16) * 4) * 4, xsrc + (sg + 16) * 4);
        CP_COMMIT();
        CP_WAIT0();
    }
    __syncthreads();

    const int rg = tid >> 4;     // row 0..15
    const int cg = tid & 15;     // col quad 0..15
    const float4* Ws4 = (const float4*)Ws;
    const float* xrow = Xrm + rg * 132;

    float aA[4] = {0.f, 0.f, 0.f, 0.f}, aB[4] = {0.f, 0.f, 0.f, 0.f};
#pragma unroll 8
    for (int k = 0; k < FIN; k += 2) {
        const float x0 = xrow[k];        // broadcast LDS (2 addrs/warp, banks differ by 4)
        const float x1 = xrow[k + 1];
        const float4 w0 = Ws4[k * 16 + cg];
        const float4 w1 = Ws4[(k + 1) * 16 + cg];
        aA[0] += x0 * w0.x; aA[1] += x0 * w0.y; aA[2] += x0 * w0.z; aA[3] += x0 * w0.w;
        aB[0] += x1 * w1.x; aB[1] += x1 * w1.y; aB[2] += x1 * w1.z; aB[3] += x1 * w1.w;
    }
    float acc[4];
#pragma unroll
    for (int c = 0; c < 4; c++) acc[c] = aA[c] + aB[c];

    // stage fp16 h transposed: hTs[f][row]
#pragma unroll
    for (int c = 0; c < 4; c++) hTs[(4 * cg + c) * 20 + rg] = f2h(acc[c]);

    const float4 a1v = ((const float4*)a1)[cg];
    const float4 a2v = ((const float4*)a2)[cg];
    float v1 = acc[0] * a1v.x + acc[1] * a1v.y + acc[2] * a1v.z + acc[3] * a1v.w;
    float v2 = acc[0] * a2v.x + acc[1] * a2v.y + acc[2] * a2v.z + acc[3] * a2v.w;
#pragma unroll
    for (int s = 8; s > 0; s >>= 1) {
        v1 += __shfl_xor_sync(0xffffffffu, v1, s, 16);
        v2 += __shfl_xor_sync(0xffffffffu, v2, s, 16);
    }

    const float s1L = v1 * LOG2E;
    const float s2L = v2 * LOG2E;
    const float E1 = ex2f(s1L), F1 = ex2f(ALPHA * s1L);
    const float E2 = ex2f(s2L), F2 = ex2f(ALPHA * s2L);
    const float E2o = __shfl_xor_sync(0xffffffffu, E2, 16);
    const float F2o = __shfl_xor_sync(0xffffffffu, F2, 16);
    if (cg == 0) {
        g_EF1p[i0 + rg] = make_uint2(pkh2(E1, E1), pkh2(F1, F1));
        if ((tid & 31) == 0)
            g_E2Fp[(i0 + rg) >> 1] = make_uint2(pkh2(E2, E2o), pkh2(F2, F2o));
    }
    __syncthreads();

    {
        const int f = tid >> 2;
        const int sg = tid & 3;
        const uint2 v = *(const uint2*)&hTs[f * 20 + 4 * sg];
        *(uint2*)(g_hT16 + (size_t)f * NN + i0 + 4 * sg) = v;
    }
}

// ===================== K2: warp-specialized fused GAT (R11 champion, unchanged) =====================
__global__ __launch_bounds__(NTHREADS, 2) void k_gat(const int* __restrict__ A,
                                                     float* __restrict__ out) {
    extern __shared__ char sm[];
    const uint32_t sb0 = smem_u32(sm);
    const uint32_t sb = (sb0 + 127u) & ~127u;
    const uint32_t mb = sb + MBAR_OFF;        // full[s]=mb+s*16, empty[s]=mb+s*16+8

    const int tid  = threadIdx.x;
    const int wid  = tid >> 5;
    const int lane = tid & 31;
    const int ib   = blockIdx.x >> 2;
    const int sk   = blockIdx.x & 3;
    const int i0   = ib * TI;
    const int j0   = sk * JH;

    if (tid == 0) {
#pragma unroll
        for (int s = 0; s < NSTAGE; s++) {
            MBAR_INIT(mb + s * 16,     64);   // full: 64 producer threads
            MBAR_INIT(mb + s * 16 + 8, 8);    // empty: 8 consumer warps
        }
    }
    __syncthreads();

    if (wid >= 8) {
        // ================= PRODUCER (2 warps, 64 threads) =================
        const int p = tid - 256;                  // 0..63
        const int ar = p >> 3;                    // A row group base (0..7)
        const int asg = p & 7;                    // A 16B segment
        const int* aSrc = A + (size_t)(i0) * NN + j0;
        const uint16_t* hSrc = g_hT16 + j0;

        for (int t = 0; t < NCH; t++) {
            const int s = t & (NSTAGE - 1);
            const int k = t >> NSTAGE_LOG2;
            if (k > 0) MBAR_WAIT(mb + s * 16 + 8, (k - 1) & 1);

            const uint32_t base = sb + (uint32_t)(s * STAGE_BYTES);
            const int jo = t * KC;
#pragma unroll
            for (int i = 0; i < 16; i++) {
                const int r = ar + 8 * i;
                CP16(base + (uint32_t)(r * A_STRIDE + asg * 4) * 4,
                     aSrc + (size_t)r * NN + jo + asg * 4);
            }
#pragma unroll
            for (int g = 0; g < 4; g++) {
                CP16(base + A_BUF + (uint32_t)(p * B_STRIDE + g * 8) * 2,
                     hSrc + (size_t)p * NN + jo + g * 8);
            }
            if (p < 8)
                CP16(base + A_BUF + B_BUF + (uint32_t)p * 16,
                     g_E2Fp + ((j0 + jo) >> 1) + p * 2);
            CPASYNC_MBAR_ARRIVE(mb + s * 16);
        }
    } else {
        // ================= CONSUMER (8 warps) =================
        const int qr = lane >> 2;
        const int qc = lane & 3;
        const int mg = wid >> 1;
        const int ng = wid & 1;

        uint32_t e1E[4], e1F[4];
#pragma unroll
        for (int k = 0; k < 4; k++) {
            const uint2 v = g_EF1p[i0 + mg * 32 + qr + 8 * k];
            e1E[k] = v.x; e1F[k] = v.y;
        }

        float acc[2][4][4];
        float accO[2][4];
#pragma unroll
        for (int mt = 0; mt < 2; mt++) {
#pragma unroll
            for (int nt = 0; nt < 4; nt++)
#pragma unroll
                for (int k = 0; k < 4; k++) acc[mt][nt][k] = 0.f;
#pragma unroll
            for (int k = 0; k < 4; k++) accO[mt][k] = 0.f;
        }
        const uint32_t kOnes = 0x3C003C00u;

        for (int t = 0; t < NCH; t++) {
            const int s = t & (NSTAGE - 1);
            const int k = t >> NSTAGE_LOG2;
            MBAR_WAIT(mb + s * 16, k & 1);

            const uint32_t aB = sb + (uint32_t)(s * STAGE_BYTES);
            const uint32_t bB = aB + A_BUF;
            const uint32_t eB = aB + A_BUF + B_BUF;

#pragma unroll
            for (int ks = 0; ks < 2; ks++) {
                const int j2 = 16 * ks + 2 * qc;
                const uint2 efL = lds_u64(eB + (uint32_t)(j2 >> 1) * 8);
                const uint2 efH = lds_u64(eB + (uint32_t)((j2 + 8) >> 1) * 8);

                uint32_t b0[4], b1[4];
#pragma unroll
                for (int nt = 0; nt < 4; nt++) {
                    const int f = ng * 32 + nt * 8 + qr;
                    const uint32_t hb = bB + (uint32_t)(f * B_STRIDE + j2) * 2;
                    b0[nt] = lds_u32(hb);
                    b1[nt] = lds_u32(hb + 16);
                }

#pragma unroll
                for (int mt = 0; mt < 2; mt++) {
                    const int r0 = mg * 32 + mt * 16 + qr;
                    const uint32_t ab = aB + (uint32_t)(r0 * A_STRIDE + j2) * 4;
                    const int2 Al0 = lds_s64(ab);
                    const int2 Ah0 = lds_s64(ab + 32);
                    const int2 Al1 = lds_s64(ab + (uint32_t)(8 * A_STRIDE) * 4);
                    const int2 Ah1 = lds_s64(ab + (uint32_t)(8 * A_STRIDE) * 4 + 32);

                    const uint32_t a0 = wpair(e1E[2*mt],   e1F[2*mt],   efL.x, efL.y, Al0.x, Al0.y);
                    const uint32_t a1 = wpair(e1E[2*mt+1], e1F[2*mt+1], efL.x, efL.y, Al1.x, Al1.y);
                    const uint32_t a2 = wpair(e1E[2*mt],   e1F[2*mt],   efH.x, efH.y, Ah0.x, Ah0.y);
                    const uint32_t a3 = wpair(e1E[2*mt+1], e1F[2*mt+1], efH.x, efH.y, Ah1.x, Ah1.y);

#pragma unroll
                    for (int nt = 0; nt < 4; nt++)
                        MMA_F16(acc[mt][nt], a0, a1, a2, a3, b0[nt], b1[nt]);
                    MMA_F16(accO[mt], a0, a1, a2, a3, kOnes, kOnes);
                }
            }
            __syncwarp();
            if (lane == 0) MBAR_ARRIVE(mb + s * 16 + 8);
        }

        // ---- epilogue: store partials ----
        if (ng == 0 && qc == 0) {
            g_wsum[sk][i0 + mg * 32 + qr]      = accO[0][0];
            g_wsum[sk][i0 + mg * 32 + qr + 8]  = accO[0][2];
            g_wsum[sk][i0 + mg * 32 + qr + 16] = accO[1][0];
            g_wsum[sk][i0 + mg * 32 + qr + 24] = accO[1][2];
        }
#pragma unroll
        for (int mt = 0; mt < 2; mt++) {
            float* pr0 = &g_part[sk][(size_t)(i0 + mg * 32 + mt * 16 + qr) * FOUT];
            float* pr1 = &g_part[sk][(size_t)(i0 + mg * 32 + mt * 16 + qr + 8) * FOUT];
#pragma unroll
            for (int nt = 0; nt < 4; nt++) {
                const int c0 = ng * 32 + nt * 8 + 2 * qc;
                *(float2*)(pr0 + c0) = make_float2(acc[mt][nt][0], acc[mt][nt][1]);
                *(float2*)(pr1 + c0) = make_float2(acc[mt][nt][2], acc[mt][nt][3]);
            }
        }
    }

    // ---- last split-K CTA for this i-block combines and divides ----
    __threadfence();
    __syncthreads();
    __shared__ int isLast;
    if (tid == 0) isLast = (atomicAdd(&g_cnt[ib], 1) == SPLIT - 1) ? 1 : 0;
    __syncthreads();
    if (isLast && tid < 256) {
        __threadfence();
#pragma unroll
        for (int k = 0; k < 8; k++) {
            const int idx4 = tid + k * 256;
            const int row = idx4 >> 4;
            const size_t e = (size_t)(i0 + row) * FOUT + (idx4 & 15) * 4;
            float4 s = *(const float4*)&g_part[0][e];
            float den = g_wsum[0][i0 + row];
#pragma unroll
            for (int p = 1; p < SPLIT; p++) {
                const float4 pp = *(const float4*)&g_part[p][e];
                s.x += pp.x; s.y += pp.y; s.z += pp.z; s.w += pp.w;
                den += g_wsum[p][i0 + row];
            }
            const float inv = 1.0f / den;
            *(float4*)(out + e) = make_float4(s.x * inv, s.y * inv, s.z * inv, s.w * inv);
        }
    }
}

extern "C" void kernel_launch(void* const* d_in, const int* in_sizes, int n_in,
                              void* d_out, int out_size) {
    const float* X  = (const float*)d_in[0];
    const int*   A  = (const int*)d_in[1];
    const float* W  = (const float*)d_in[2];
    const float* a1 = (const float*)d_in[3];
    const float* a2 = (const float*)d_in[4];
    float* out = (float*)d_out;

    cudaFuncSetAttribute(k_gat, cudaFuncAttributeMaxDynamicSharedMemorySize, GAT_SMEM);

    k_proj<<<NN / 16, 256>>>(X, W, a1, a2);
    k_gat<<<(NN / TI) * SPLIT, NTHREADS, GAT_SMEM>>>(A, out);
}